// round 2
// baseline (speedup 1.0000x reference)
#include <cuda_runtime.h>
#include <math.h>

// ---------------- static config ----------------
#define Bv 4
#define Lv 4096
#define Dv 1024
#define Kv 32
#define Hv 32
#define Av 4
#define CKv 4
#define DIv 1024          // d_inner
#define ZCv 2080          // 2*DI + K
#define BLv (Bv*Lv)       // 16384

#define NSEG 32
#define SEGLEN (Lv/NSEG)  // 128

// ---------------- scratch (device globals; no allocation) ----------------
__device__ float g_z[(size_t)BLv * ZCv];        // in_proj output   (~136 MB)
__device__ float g_merged[(size_t)BLv * ZCv];   // [den|re|im], cumsummed in place
__device__ float g_gate[(size_t)BLv * DIv];     // silu gate        (~64 MB)
__device__ float g_h[(size_t)BLv * DIv];        // y * gate         (~64 MB)
__device__ float g_part[Bv][NSEG][ZCv];         // segment partial sums

// ---------------- fp32 SGEMM: C[M,N] = A[M,K] @ B[K,N], row-major ----------------
// 128x128 tile, BK=8, 256 threads, 8x8 per thread. M%128==0, K%8==0 assumed; N guarded.
__global__ __launch_bounds__(256) void sgemm128(const float* __restrict__ A,
                                                const float* __restrict__ B,
                                                float* __restrict__ C,
                                                int M, int N, int K) {
    __shared__ float As[8][128];
    __shared__ float Bs[8][128];
    const int tid = threadIdx.x;
    const int tx = tid & 15;          // 0..15 -> N direction
    const int ty = tid >> 4;          // 0..15 -> M direction
    const int bx = blockIdx.x;        // N tile
    const int by = blockIdx.y;        // M tile

    const int aRow = tid >> 1;              // 0..127
    const int aCol = (tid & 1) * 4;         // 0 or 4
    const int bRow = tid >> 5;              // 0..7
    const int bCol = (tid & 31) * 4;        // 0..124

    const float* Aptr = A + (size_t)(by * 128 + aRow) * K;
    float acc[8][8];
    #pragma unroll
    for (int i = 0; i < 8; i++)
        #pragma unroll
        for (int j = 0; j < 8; j++) acc[i][j] = 0.f;

    for (int k0 = 0; k0 < K; k0 += 8) {
        // A tile (transposed into As[k][m])
        float4 av = *(const float4*)(Aptr + k0 + aCol);
        As[aCol + 0][aRow] = av.x;
        As[aCol + 1][aRow] = av.y;
        As[aCol + 2][aRow] = av.z;
        As[aCol + 3][aRow] = av.w;
        // B tile (guard N edge)
        int gcol = bx * 128 + bCol;
        float4 bv = make_float4(0.f, 0.f, 0.f, 0.f);
        if (gcol + 3 < N) {
            bv = *(const float4*)(B + (size_t)(k0 + bRow) * N + gcol);
        } else {
            float* p = (float*)&bv;
            #pragma unroll
            for (int i = 0; i < 4; i++)
                if (gcol + i < N) p[i] = B[(size_t)(k0 + bRow) * N + gcol + i];
        }
        *(float4*)&Bs[bRow][bCol] = bv;
        __syncthreads();

        #pragma unroll
        for (int kk = 0; kk < 8; kk++) {
            float4 a0 = *(const float4*)&As[kk][ty * 8];
            float4 a1 = *(const float4*)&As[kk][ty * 8 + 4];
            float4 b0 = *(const float4*)&Bs[kk][tx * 8];
            float4 b1 = *(const float4*)&Bs[kk][tx * 8 + 4];
            float ra[8] = {a0.x, a0.y, a0.z, a0.w, a1.x, a1.y, a1.z, a1.w};
            float rb[8] = {b0.x, b0.y, b0.z, b0.w, b1.x, b1.y, b1.z, b1.w};
            #pragma unroll
            for (int i = 0; i < 8; i++)
                #pragma unroll
                for (int j = 0; j < 8; j++)
                    acc[i][j] = fmaf(ra[i], rb[j], acc[i][j]);
        }
        __syncthreads();
    }

    const int rowC = by * 128 + ty * 8;
    const int colC = bx * 128 + tx * 8;
    #pragma unroll
    for (int i = 0; i < 8; i++) {
        size_t rbase = (size_t)(rowC + i) * N;
        if (colC + 7 < N) {
            *(float4*)(C + rbase + colC)     = make_float4(acc[i][0], acc[i][1], acc[i][2], acc[i][3]);
            *(float4*)(C + rbase + colC + 4) = make_float4(acc[i][4], acc[i][5], acc[i][6], acc[i][7]);
        } else {
            #pragma unroll
            for (int j = 0; j < 8; j++)
                if (colC + j < N) C[rbase + colC + j] = acc[i][j];
        }
    }
}

// ---------------- causal depthwise conv + feature transform ----------------
// One block per (b,l). Produces merged = [p_w(32) | p_w*cos(phi)(1024) | p_w*sin(phi)(1024)]
// and the silu gate.
__global__ __launch_bounds__(256) void transform_kernel(const float* __restrict__ ck,      // [CK][ZC]
                                                        const float* __restrict__ theta,   // [1024]
                                                        const float* __restrict__ decay,   // [28]
                                                        const float* __restrict__ anchor,  // [4]
                                                        const float* __restrict__ score) { // [32]
    const int bl = blockIdx.x;
    const int b = bl >> 12;          // / 4096
    const int l = bl & (Lv - 1);
    const int tid = threadIdx.x;
    __shared__ float pw_s[Kv];

    const size_t row = (size_t)bl * ZCv;     // z row for position l

    // scores -> p_w (channels 2048..2079)
    if (tid < Kv) {
        int k = tid;
        int c = 2 * DIv + k;
        float s = 0.f;
        #pragma unroll
        for (int j = 0; j < CKv; j++) {
            int ll = l - (CKv - 1) + j;
            if (ll >= 0) s += ck[j * ZCv + c] * g_z[row + (long long)(ll - l) * ZCv + c];
        }
        float lw;
        if (k < Kv - Av) {
            float slope = log1pf(expf(decay[k]));
            lw = -slope * (float)(Lv - 1 - l);
        } else {
            float slope = log1pf(expf(anchor[k - (Kv - Av)]));
            lw = -slope * (float)l;
        }
        float pw = expf(score[k] * s + lw);
        pw_s[k] = pw;
        g_merged[row + k] = pw;
    }
    __syncthreads();

    for (int c = tid; c < DIv; c += 256) {
        // x_val channel c
        float xv = 0.f, gv = 0.f;
        #pragma unroll
        for (int j = 0; j < CKv; j++) {
            int ll = l - (CKv - 1) + j;
            if (ll >= 0) {
                long long off = (long long)(ll - l) * ZCv;
                xv += ck[j * ZCv + c]       * g_z[row + off + c];
                gv += ck[j * ZCv + DIv + c] * g_z[row + off + DIv + c];
            }
        }
        float phi = xv * theta[c];
        float sn, cs;
        sincosf(phi, &sn, &cs);
        float pw = pw_s[c >> 5];
        g_merged[row + Kv + c]       = pw * cs;
        g_merged[row + Kv + DIv + c] = pw * sn;
        g_gate[(size_t)bl * DIv + c] = gv / (1.f + expf(-gv));
    }
}

// ---------------- segmented cumsum over L, in place on g_merged ----------------
__global__ void scan_seg_sum() {
    int c = blockIdx.x * 256 + threadIdx.x;
    if (c >= ZCv) return;
    int seg = blockIdx.y, b = blockIdx.z;
    size_t base = ((size_t)b * Lv + (size_t)seg * SEGLEN) * ZCv + c;
    float s = 0.f;
    #pragma unroll 4
    for (int i = 0; i < SEGLEN; i++) s += g_merged[base + (size_t)i * ZCv];
    g_part[b][seg][c] = s;
}

__global__ void scan_offsets() {
    int c = blockIdx.x * 256 + threadIdx.x;
    if (c >= ZCv) return;
    int b = blockIdx.y;
    float run = 0.f;
    for (int s = 0; s < NSEG; s++) {
        float v = g_part[b][s][c];
        g_part[b][s][c] = run;
        run += v;
    }
}

__global__ void scan_apply() {
    int c = blockIdx.x * 256 + threadIdx.x;
    if (c >= ZCv) return;
    int seg = blockIdx.y, b = blockIdx.z;
    float carry = g_part[b][seg][c];
    size_t base = ((size_t)b * Lv + (size_t)seg * SEGLEN) * ZCv + c;
    #pragma unroll 4
    for (int i = 0; i < SEGLEN; i++) {
        size_t idx = base + (size_t)i * ZCv;
        carry += g_merged[idx];
        g_merged[idx] = carry;
    }
}

// ---------------- normalize + complex mix (32x32) + gate ----------------
// One block per (b,l); warp w handles heads {w, w+8, w+16, w+24}; lane = h.
__global__ __launch_bounds__(256) void mix_kernel(const float* __restrict__ W_re,   // [32][32]
                                                  const float* __restrict__ W_im,   // [32][32]
                                                  const float* __restrict__ nscale) // [64]
{
    const int bl = blockIdx.x;
    const int tid = threadIdx.x;
    const int lane = tid & 31;
    const int w = tid >> 5;
    __shared__ float Wr[32][33], Wi[32][33], ns[64];
    for (int i = tid; i < 1024; i += 256) {
        Wr[i >> 5][i & 31] = W_re[i];
        Wi[i >> 5][i & 31] = W_im[i];
    }
    if (tid < 64) ns[tid] = nscale[tid];
    __syncthreads();

    const size_t base = (size_t)bl * ZCv;
    for (int k = w; k < Kv; k += 8) {
        float den = g_merged[base + k];
        float inv = 1.f / fmaxf(den, 1e-4f);
        float re = g_merged[base + Kv + k * 32 + lane] * inv;
        float im = g_merged[base + Kv + DIv + k * 32 + lane] * inv;
        float ss = re * re + im * im;
        #pragma unroll
        for (int o = 16; o > 0; o >>= 1) ss += __shfl_xor_sync(0xffffffffu, ss, o);
        float rs = rsqrtf(ss * (1.f / 64.f) + 1e-5f);
        float a  = re * rs * ns[lane];
        float bb = im * rs * ns[32 + lane];
        float y = 0.f;
        #pragma unroll
        for (int h = 0; h < 32; h++) {
            y = fmaf(__shfl_sync(0xffffffffu, a,  h), Wr[h][lane], y);
            y = fmaf(__shfl_sync(0xffffffffu, bb, h), Wi[h][lane], y);
        }
        size_t gi = (size_t)bl * DIv + k * 32 + lane;
        g_h[gi] = y * g_gate[gi];
    }
}

// ---------------- launch ----------------
extern "C" void kernel_launch(void* const* d_in, const int* in_sizes, int n_in,
                              void* d_out, int out_size) {
    const float* x      = (const float*)d_in[0];   // [4,4096,1024]
    const float* W_in   = (const float*)d_in[1];   // [1024,2080]
    const float* convk  = (const float*)d_in[2];   // [4,1,2080]
    const float* theta  = (const float*)d_in[3];   // [32*32]
    const float* decay  = (const float*)d_in[4];   // [28]
    const float* anchor = (const float*)d_in[5];   // [4]
    const float* score  = (const float*)d_in[6];   // [32]
    const float* W_re   = (const float*)d_in[7];   // [32,32]
    const float* W_im   = (const float*)d_in[8];   // [32,32]
    const float* nscale = (const float*)d_in[9];   // [64]
    const float* W_out  = (const float*)d_in[10];  // [1024,1024]
    float* out = (float*)d_out;                    // [4,4096,1024]

    float* zbuf; cudaGetSymbolAddress((void**)&zbuf, g_z);
    float* hbuf; cudaGetSymbolAddress((void**)&hbuf, g_h);

    // 1) z = x @ W_in    [16384,1024] @ [1024,2080]
    {
        dim3 grid((ZCv + 127) / 128, BLv / 128);
        sgemm128<<<grid, 256>>>(x, W_in, zbuf, BLv, ZCv, Dv);
    }
    // 2) conv + features
    transform_kernel<<<BLv, 256>>>(convk, theta, decay, anchor, score);
    // 3) cumsum over L
    {
        dim3 g1((ZCv + 255) / 256, NSEG, Bv);
        scan_seg_sum<<<g1, 256>>>();
        dim3 g2((ZCv + 255) / 256, Bv);
        scan_offsets<<<g2, 256>>>();
        scan_apply<<<g1, 256>>>();
    }
    // 4) normalize + mix + gate
    mix_kernel<<<BLv, 256>>>(W_re, W_im, nscale);
    // 5) out = h @ W_out  [16384,1024] @ [1024,1024]
    {
        dim3 grid((Dv + 127) / 128, BLv / 128);
        sgemm128<<<grid, 256>>>(hbuf, W_out, out, BLv, Dv, Dv);
    }
}